// round 10
// baseline (speedup 1.0000x reference)
#include <cuda_runtime.h>
#include <cuda_bf16.h>
#include <math.h>

#define NN 50000
#define EE 400000
#define ET 450000   // EE + NN self loops
#define EPSN 1e-5f
#define XPAD 66     // even -> aligned LDS.64 row pairs

// ---------------- scratch (device globals) -----------------------------------
__device__ float g_A[(size_t)NN * 128];       // h2
__device__ float g_B[(size_t)NN * 128];       // gat2 raw
__device__ float g_Z[(size_t)NN * 16];        // z[d][h][0..2] (float4 per (d,h)), normalized
__device__ float4 g_nd1[(size_t)NN * 2];      // [n]: {x0,x1,x2,_}, {alS0..3}
__device__ float g_alD[(size_t)NN * 4];
__device__ float g_alS2[(size_t)NN * 2];
__device__ float g_alD2[(size_t)NN * 2];
__device__ float g_colstats[512];             // layer2 sums (self-cleaned in gath1z)
__device__ float g_zmom[36];                  // per head: S0,S1,S2,M00,M01,M02,M11,M12,M22
__device__ float g_eamsum[2];
__device__ float g_eamean[2];
__device__ float g_v1[8];
__device__ float g_v2[4];
__device__ float g_uS1[12], g_uD1[12];
__device__ float g_uS2[512], g_uD2[512];      // [k*2+h]
// CSR
__device__ int g_cnt[NN];                     // counts (self-cleaned in gath1z)
__device__ int g_rowptr[NN + 1];              // post-fill: rowptr[d] == start of d+1
__device__ float4 g_csr[ET];                  // {src_bits, ea0, ea1, pad} in CSR order

// f32x2 packed helpers
#define FMA2(acc, a, b) asm("fma.rn.f32x2 %0, %1, %2, %0;" : "+l"(acc) : "l"(a), "l"(b))
#define BCAST2(p, f)    asm("mov.b64 %0, {%1, %1};" : "=l"(p) : "f"(f))
#define UNPK2(lo, hi, p) asm("mov.b64 {%0, %1}, %2;" : "=f"(lo), "=f"(hi) : "l"(p))

// ---------------- fused: dst-degree count + edge_attr mean -------------------
__global__ void k_cm(const int* __restrict__ ei, const float* __restrict__ ea) {
    float s0 = 0.f, s1 = 0.f;
    int st = gridDim.x * blockDim.x;
    for (int e = blockIdx.x * blockDim.x + threadIdx.x; e < ET; e += st) {
        int d = (e < EE) ? ei[EE + e] : (e - EE);
        atomicAdd(&g_cnt[d], 1);
        if (e < EE) { s0 += ea[2 * e]; s1 += ea[2 * e + 1]; }
    }
    for (int o = 16; o; o >>= 1) {
        s0 += __shfl_down_sync(0xFFFFFFFFu, s0, o);
        s1 += __shfl_down_sync(0xFFFFFFFFu, s1, o);
    }
    __shared__ float sh[16];
    int lane = threadIdx.x & 31, wid = threadIdx.x >> 5;
    if (lane == 0) { sh[wid] = s0; sh[8 + wid] = s1; }
    __syncthreads();
    if (threadIdx.x == 0) {
        float a = 0.f, b = 0.f;
        for (int w = 0; w < 8; w++) { a += sh[w]; b += sh[8 + w]; }
        atomicAdd(&g_eamsum[0], a);
        atomicAdd(&g_eamsum[1], b);
    }
}

// ---------------- merged precomputes (4 blocks x 256) ------------------------
__global__ void k_prep(const float* __restrict__ We1, const float* __restrict__ ae1,
                       const float* __restrict__ We2, const float* __restrict__ ae2,
                       const float* __restrict__ W1, const float* __restrict__ as1,
                       const float* __restrict__ ad1,
                       const float* __restrict__ W2, const float* __restrict__ as2,
                       const float* __restrict__ ad2) {
    int gt = blockIdx.x * 256 + threadIdx.x;
    {   // uS2/uD2 over all 4 blocks (1024 threads)
        int which = gt >> 9;
        int kk = (gt & 511) >> 1, h = gt & 1;
        const float* a = which ? ad2 : as2;
        float s = 0.f;
        for (int d = 0; d < 64; d++) s += W2[kk * 128 + h * 64 + d] * a[h * 64 + d];
        if (which) g_uD2[kk * 2 + h] = s; else g_uS2[kk * 2 + h] = s;
    }
    if (blockIdx.x != 0) return;
    int t = threadIdx.x;
    if (t < 8) {
        int h = t >> 1, f = t & 1;
        float s = 0.f;
        for (int d = 0; d < 64; d++) s += We1[f * 256 + h * 64 + d] * ae1[h * 64 + d];
        g_v1[t] = s;
    } else if (t < 12) {
        int tt = t - 8, h = tt >> 1, f = tt & 1;
        float s = 0.f;
        for (int d = 0; d < 64; d++) s += We2[f * 128 + h * 64 + d] * ae2[h * 64 + d];
        g_v2[tt] = s;
    } else if (t < 24) {
        int idx = t - 12, f = idx >> 2, h = idx & 3;
        float s = 0.f;
        for (int d = 0; d < 64; d++) s += W1[f * 256 + h * 64 + d] * as1[h * 64 + d];
        g_uS1[idx] = s;
    } else if (t < 36) {
        int idx = t - 24, f = idx >> 2, h = idx & 3;
        float s = 0.f;
        for (int d = 0; d < 64; d++) s += W1[f * 256 + h * 64 + d] * ad1[h * 64 + d];
        g_uD1[idx] = s;
    }
    __syncthreads();
    if (t == 0) {
        g_eamean[0] = g_eamsum[0] / (float)EE;
        g_eamean[1] = g_eamsum[1] / (float)EE;
    }
}

// ---------------- single-kernel scan (+ fused layer1 node data) --------------
__global__ void k_scan(const float* __restrict__ x) {
    __shared__ int sh[256];
    __shared__ int swr[8];
    int tid = threadIdx.x;
    int i = blockIdx.x * 256 + tid;

    int limit = blockIdx.x << 8;
    int acc = 0;
    for (int t = tid; t < limit; t += 256) acc += g_cnt[t];
    for (int o = 16; o; o >>= 1) acc += __shfl_down_sync(0xFFFFFFFFu, acc, o);
    if ((tid & 31) == 0) swr[tid >> 5] = acc;

    int v = (i < NN) ? g_cnt[i] : 0;
    sh[tid] = v;
    __syncthreads();
    for (int o = 1; o < 256; o <<= 1) {
        int t = (tid >= o) ? sh[tid - o] : 0;
        __syncthreads();
        sh[tid] += t;
        __syncthreads();
    }
    int base = swr[0] + swr[1] + swr[2] + swr[3] + swr[4] + swr[5] + swr[6] + swr[7];
    if (i < NN) g_rowptr[i] = base + sh[tid] - v;   // exclusive start

    // independent: layer1 per-node packed data {x | alS} and alD
    if (i < NN) {
        float x0 = __ldg(&x[3 * i]), x1 = __ldg(&x[3 * i + 1]), x2 = __ldg(&x[3 * i + 2]);
        float4 s, d;
        s.x = x0 * g_uS1[0] + x1 * g_uS1[4] + x2 * g_uS1[8];
        s.y = x0 * g_uS1[1] + x1 * g_uS1[5] + x2 * g_uS1[9];
        s.z = x0 * g_uS1[2] + x1 * g_uS1[6] + x2 * g_uS1[10];
        s.w = x0 * g_uS1[3] + x1 * g_uS1[7] + x2 * g_uS1[11];
        d.x = x0 * g_uD1[0] + x1 * g_uD1[4] + x2 * g_uD1[8];
        d.y = x0 * g_uD1[1] + x1 * g_uD1[5] + x2 * g_uD1[9];
        d.z = x0 * g_uD1[2] + x1 * g_uD1[6] + x2 * g_uD1[10];
        d.w = x0 * g_uD1[3] + x1 * g_uD1[7] + x2 * g_uD1[11];
        g_nd1[(size_t)i * 2]     = make_float4(x0, x1, x2, 0.f);
        g_nd1[(size_t)i * 2 + 1] = s;
        *(float4*)&g_alD[i * 4] = d;
    }
}

// ---------------- fill: rowptr self-advance, packed record, 2 edges/thread ---
__global__ void k_fill(const int* __restrict__ ei, const float* __restrict__ ea) {
    int e0 = (blockIdx.x * blockDim.x + threadIdx.x) * 2;
#pragma unroll
    for (int u = 0; u < 2; u++) {
        int e = e0 + u;
        if (e >= ET) break;
        int s, d;
        float2 eav;
        if (e < EE) {
            s = ei[e]; d = ei[EE + e];
            eav = *(const float2*)&ea[2 * e];
        } else {
            s = e - EE; d = s;
            eav = make_float2(g_eamean[0], g_eamean[1]);
        }
        int pos = atomicAdd(&g_rowptr[d], 1);
        g_csr[pos] = make_float4(__int_as_float(s), eav.x, eav.y, 0.f);
    }
}
// After k_fill: g_rowptr[d] == start of node d+1. Range of d = [d?rowptr[d-1]:0, rowptr[d]).

// ---------------- layer1 gather: thread per node, all 4 heads, plain loop ----
__global__ void __launch_bounds__(256) k_gath1z() {
    __shared__ float smom[8][36];
    int n = blockIdx.x * 256 + threadIdx.x;
    if (blockIdx.x == 0) {    // self-clean for later consumers
        g_colstats[threadIdx.x] = 0.f;
        g_colstats[256 + threadIdx.x] = 0.f;
    }
    bool valid = n < NN;
    if (valid) g_cnt[n] = 0;  // ready for next replay's k_cm
    int p0 = 0, p1 = 0;
    if (valid) { p0 = n ? g_rowptr[n - 1] : 0; p1 = g_rowptr[n]; }
    float4 aD = valid ? *(const float4*)&g_alD[n * 4] : make_float4(0.f, 0.f, 0.f, 0.f);
    float v10 = g_v1[0], v11 = g_v1[1], v12 = g_v1[2], v13 = g_v1[3];
    float v14 = g_v1[4], v15 = g_v1[5], v16 = g_v1[6], v17 = g_v1[7];
    float z00 = 0.f, z01 = 0.f, z02 = 0.f, ws0 = 0.f;
    float z10 = 0.f, z11 = 0.f, z12 = 0.f, ws1 = 0.f;
    float z20 = 0.f, z21 = 0.f, z22 = 0.f, ws2 = 0.f;
    float z30 = 0.f, z31 = 0.f, z32 = 0.f, ws3 = 0.f;
#pragma unroll 2
    for (int pos = p0; pos < p1; pos++) {
        float4 c = __ldg(&g_csr[pos]);
        int s = __float_as_int(c.x);
        float4 nx = __ldg(&g_nd1[(size_t)s * 2]);
        float4 na = __ldg(&g_nd1[(size_t)s * 2 + 1]);
        float a0 = na.x + aD.x + c.y * v10 + c.z * v11;
        float a1 = na.y + aD.y + c.y * v12 + c.z * v13;
        float a2 = na.z + aD.z + c.y * v14 + c.z * v15;
        float a3 = na.w + aD.w + c.y * v16 + c.z * v17;
        a0 = a0 > 0.f ? a0 : 0.2f * a0;
        a1 = a1 > 0.f ? a1 : 0.2f * a1;
        a2 = a2 > 0.f ? a2 : 0.2f * a2;
        a3 = a3 > 0.f ? a3 : 0.2f * a3;
        float w0 = __expf(a0), w1 = __expf(a1), w2 = __expf(a2), w3 = __expf(a3);
        ws0 += w0; z00 += w0 * nx.x; z01 += w0 * nx.y; z02 += w0 * nx.z;
        ws1 += w1; z10 += w1 * nx.x; z11 += w1 * nx.y; z12 += w1 * nx.z;
        ws2 += w2; z20 += w2 * nx.x; z21 += w2 * nx.y; z22 += w2 * nx.z;
        ws3 += w3; z30 += w3 * nx.x; z31 += w3 * nx.y; z32 += w3 * nx.z;
    }
    float r;
    r = valid ? 1.f / ws0 : 0.f; z00 *= r; z01 *= r; z02 *= r;
    r = valid ? 1.f / ws1 : 0.f; z10 *= r; z11 *= r; z12 *= r;
    r = valid ? 1.f / ws2 : 0.f; z20 *= r; z21 *= r; z22 *= r;
    r = valid ? 1.f / ws3 : 0.f; z30 *= r; z31 *= r; z32 *= r;
    if (valid) {
        *(float4*)&g_Z[(size_t)n * 16 + 0]  = make_float4(z00, z01, z02, 0.f);
        *(float4*)&g_Z[(size_t)n * 16 + 4]  = make_float4(z10, z11, z12, 0.f);
        *(float4*)&g_Z[(size_t)n * 16 + 8]  = make_float4(z20, z21, z22, 0.f);
        *(float4*)&g_Z[(size_t)n * 16 + 12] = make_float4(z30, z31, z32, 0.f);
    }

    // per-head moments: warp reduce, block reduce, 36 atomics/block
    int lane = threadIdx.x & 31, wi = threadIdx.x >> 5;
    float zz[4][3] = {{z00, z01, z02}, {z10, z11, z12}, {z20, z21, z22}, {z30, z31, z32}};
#pragma unroll
    for (int h = 0; h < 4; h++) {
        float a = zz[h][0], b = zz[h][1], cq = zz[h][2];
        float p[9] = {a, b, cq, a * a, a * b, a * cq, b * b, b * cq, cq * cq};
#pragma unroll
        for (int i = 0; i < 9; i++) {
            float v = p[i];
            v += __shfl_down_sync(0xFFFFFFFFu, v, 16);
            v += __shfl_down_sync(0xFFFFFFFFu, v, 8);
            v += __shfl_down_sync(0xFFFFFFFFu, v, 4);
            v += __shfl_down_sync(0xFFFFFFFFu, v, 2);
            v += __shfl_down_sync(0xFFFFFFFFu, v, 1);
            p[i] = v;
        }
        if (lane == 0) {
#pragma unroll
            for (int i = 0; i < 9; i++) smom[wi][h * 9 + i] = p[i];
        }
    }
    __syncthreads();
    if (threadIdx.x < 36) {
        float s = 0.f;
#pragma unroll
        for (int w = 0; w < 8; w++) s += smom[w][threadIdx.x];
        atomicAdd(&g_zmom[threadIdx.x], s);
    }
}

// ---------------- fused GEMM2: inline layer1 norm, z-expand, f32x2 FMA -------
__global__ void __launch_bounds__(256) k_gemm2f(const float* __restrict__ W1,
                                                const float* __restrict__ W2,
                                                const float* __restrict__ b1,
                                                const float* __restrict__ ms1,
                                                const float* __restrict__ gw1,
                                                const float* __restrict__ gb1) {
    extern __shared__ float xs[];          // [256][XPAD] k-major
    __shared__ float cs[256], cf[256], us[512], ud[512], w1s[768], zs[64 * 16];
    __shared__ float zm[36];
    int tid = threadIdx.x;
    us[tid] = g_uS2[tid]; us[256 + tid] = g_uS2[256 + tid];
    ud[tid] = g_uD2[tid]; ud[256 + tid] = g_uD2[256 + tid];
    w1s[tid] = W1[tid]; w1s[256 + tid] = W1[256 + tid]; w1s[512 + tid] = W1[512 + tid];
    if (tid < 36) zm[tid] = g_zmom[tid];

    int r0 = blockIdx.x * 64;
    {   // stage z rows: 64 nodes x 4 float4
        int row = tid >> 2, part = tid & 3;
        float4 zv = make_float4(0.f, 0.f, 0.f, 0.f);
        if (r0 + row < NN) zv = *(const float4*)&g_Z[(size_t)(r0 + row) * 16 + part * 4];
        *(float4*)&zs[(row * 4 + part) * 4] = zv;
    }
    __syncthreads();

    {   // inline layer-1 GraphNorm coefficients from z-moments
        int j = tid, h = j >> 6;
        float w0 = w1s[j], w1 = w1s[256 + j], w2 = w1s[512 + j];
        const float* m = zm + h * 9;
        float sum = w0 * m[0] + w1 * m[1] + w2 * m[2];
        float sq  = w0 * w0 * m[3] + w1 * w1 * m[6] + w2 * w2 * m[8]
                  + 2.f * (w0 * w1 * m[4] + w0 * w2 * m[5] + w1 * w2 * m[7]);
        float invN = 1.0f / NN;
        float bj = b1[j];
        float mean = sum * invN + bj;
        float cp = bj - mean * ms1[j];
        float var = sq * invN + 2.f * cp * (sum * invN) + cp * cp;
        float rstd = rsqrtf(var + EPSN);
        cs[j] = gw1[j] * rstd;
        cf[j] = cp * gw1[j] * rstd + gb1[j];
    }
    __syncthreads();

    // expand + norm + ELU into xs (k-major, transposed)
    for (int idx = tid; idx < 64 * 64; idx += 256) {
        int r = idx >> 6, kq = idx & 63;
        int k4 = kq * 4, h = kq >> 4;
        const float* zp = zs + (r * 4 + h) * 4;
        float z0 = zp[0], z1 = zp[1], z2 = zp[2];
#pragma unroll
        for (int cc = 0; cc < 4; cc++) {
            int c = k4 + cc;
            float v = z0 * w1s[c] + z1 * w1s[256 + c] + z2 * w1s[512 + c];
            float y = v * cs[c] + cf[c];
            y = y > 0.f ? y : expm1f(y);
            xs[c * XPAD + r] = y;
        }
    }
    __syncthreads();

    int tx = tid & 31, ty = tid >> 5;
    int c0 = tx * 4, rb = ty * 8;
    unsigned long long acc[4][4];
#pragma unroll
    for (int p = 0; p < 4; p++)
#pragma unroll
        for (int c = 0; c < 4; c++) acc[p][c] = 0ull;

    const float* W2p = W2 + c0;
#pragma unroll 4
    for (int k = 0; k < 256; k++) {
        const unsigned long long* xq = (const unsigned long long*)(xs + k * XPAD + rb);
        float4 w = __ldg((const float4*)(W2p + k * 128));
        unsigned long long xp0 = xq[0], xp1 = xq[1], xp2 = xq[2], xp3 = xq[3];
        unsigned long long wp;
        BCAST2(wp, w.x);
        FMA2(acc[0][0], xp0, wp); FMA2(acc[1][0], xp1, wp); FMA2(acc[2][0], xp2, wp); FMA2(acc[3][0], xp3, wp);
        BCAST2(wp, w.y);
        FMA2(acc[0][1], xp0, wp); FMA2(acc[1][1], xp1, wp); FMA2(acc[2][1], xp2, wp); FMA2(acc[3][1], xp3, wp);
        BCAST2(wp, w.z);
        FMA2(acc[0][2], xp0, wp); FMA2(acc[1][2], xp1, wp); FMA2(acc[2][2], xp2, wp); FMA2(acc[3][2], xp3, wp);
        BCAST2(wp, w.w);
        FMA2(acc[0][3], xp0, wp); FMA2(acc[1][3], xp1, wp); FMA2(acc[2][3], xp2, wp); FMA2(acc[3][3], xp3, wp);
    }

#pragma unroll
    for (int p = 0; p < 4; p++) {
        int row = r0 + rb + 2 * p;
        float l0, h0, l1, h1, l2, h2v, l3, h3;
        UNPK2(l0, h0, acc[p][0]);
        UNPK2(l1, h1, acc[p][1]);
        UNPK2(l2, h2v, acc[p][2]);
        UNPK2(l3, h3, acc[p][3]);
        if (row < NN)     *(float4*)(g_A + (size_t)row * 128 + c0)       = make_float4(l0, l1, l2, l3);
        if (row + 1 < NN) *(float4*)(g_A + (size_t)(row + 1) * 128 + c0) = make_float4(h0, h1, h2v, h3);
    }

    {   // layer-2 attention logits from the normalized tile
        int row = tid >> 2, q = tid & 3;
        int grow = r0 + row;
        const float* uu = (q < 2) ? (us + q) : (ud + (q - 2));
        float s = 0.f;
#pragma unroll 8
        for (int k = 0; k < 256; k++)
            s += xs[k * XPAD + row] * uu[k * 2];
        if (grow < NN) {
            if (q < 2) g_alS2[grow * 2 + q] = s;
            else       g_alD2[grow * 2 + (q - 2)] = s;
        }
    }
}

// ---------------- layer2 gather: warp per node, fused alpha, plain loop ------
__global__ void __launch_bounds__(256) k_gath2() {
    if (blockIdx.x == 0) {   // self-clean for next replay
        if (threadIdx.x < 36) g_zmom[threadIdx.x] = 0.f;
        if (threadIdx.x >= 36 && threadIdx.x < 38) g_eamsum[threadIdx.x - 36] = 0.f;
    }
    int d = (blockIdx.x * 256 + threadIdx.x) >> 5;
    if (d >= NN) return;
    int lane = threadIdx.x & 31;
    int j = lane * 4;
    int h = lane >> 4;
    int p0 = d ? g_rowptr[d - 1] : 0;
    int p1 = g_rowptr[d];
    float v20 = g_v2[2 * h], v21 = g_v2[2 * h + 1];
    float aD = g_alD2[d * 2 + h];
    float4 acc = make_float4(0.f, 0.f, 0.f, 0.f);
    float ws = 0.f;
#pragma unroll 2
    for (int pos = p0; pos < p1; pos++) {
        float4 c = __ldg(&g_csr[pos]);
        int s = __float_as_int(c.x);
        float a = __ldg(&g_alS2[s * 2 + h]) + aD + c.y * v20 + c.z * v21;
        a = a > 0.f ? a : 0.2f * a;
        float w = __expf(a);
        float4 v = *(const float4*)(g_A + (size_t)s * 128 + j);
        ws += w;
        acc.x += v.x * w; acc.y += v.y * w; acc.z += v.z * w; acc.w += v.w * w;
    }
    float r = 1.f / ws;
    acc.x *= r; acc.y *= r; acc.z *= r; acc.w *= r;
    *(float4*)(g_B + (size_t)d * 128 + j) = acc;
}

// ---------------- layer2 GraphNorm column stats ------------------------------
__global__ void k_colsum2(const float* __restrict__ X, int rpb) {
    int j = threadIdx.x;   // 128
    int r0 = blockIdx.x * rpb, r1 = min(r0 + rpb, NN);
    float s = 0.f, q = 0.f;
    for (int r = r0; r < r1; r++) {
        float v = X[(size_t)r * 128 + j];
        s += v;
        q += v * v;
    }
    atomicAdd(&g_colstats[j], s);
    atomicAdd(&g_colstats[256 + j], q);
}

// ---------------- classifier (inline layer2 norm + ELU) ----------------------
__global__ void k_cls(const float* __restrict__ Wc, const float* __restrict__ bc,
                      const float* __restrict__ b2, const float* __restrict__ ms2,
                      const float* __restrict__ gw2, const float* __restrict__ gb2,
                      float* __restrict__ out) {
    __shared__ float wc[128 * 13];
    __shared__ float sbc[13];
    __shared__ float cs[128], cf[128];
    for (int i = threadIdx.x; i < 128 * 13; i += 256) wc[i] = Wc[i];
    if (threadIdx.x < 13) sbc[threadIdx.x] = bc[threadIdx.x];
    if (threadIdx.x < 128) {
        int j = threadIdx.x;
        float invN = 1.0f / NN;
        float sum = g_colstats[j], sq = g_colstats[256 + j];
        float bj = b2[j];
        float m = sum * invN + bj;
        float cp = bj - m * ms2[j];
        float var = sq * invN + 2.f * cp * (sum * invN) + cp * cp;
        float rstd = rsqrtf(var + EPSN);
        cs[j] = gw2[j] * rstd;
        cf[j] = cp * gw2[j] * rstd + gb2[j];
    }
    __syncthreads();
    int warp = (blockIdx.x * 256 + threadIdx.x) >> 5;
    int lane = threadIdx.x & 31;
    int nw = (gridDim.x * 256) >> 5;
    for (int n = warp; n < NN; n += nw) {
        float4 hv = *(const float4*)(g_B + (size_t)n * 128 + lane * 4);
        int kb = lane * 4;
        float y0 = hv.x * cs[kb + 0] + cf[kb + 0]; y0 = y0 > 0.f ? y0 : expm1f(y0);
        float y1 = hv.y * cs[kb + 1] + cf[kb + 1]; y1 = y1 > 0.f ? y1 : expm1f(y1);
        float y2 = hv.z * cs[kb + 2] + cf[kb + 2]; y2 = y2 > 0.f ? y2 : expm1f(y2);
        float y3 = hv.w * cs[kb + 3] + cf[kb + 3]; y3 = y3 > 0.f ? y3 : expm1f(y3);
#pragma unroll
        for (int c = 0; c < 13; c++) {
            float p = y0 * wc[kb * 13 + c] + y1 * wc[(kb + 1) * 13 + c]
                    + y2 * wc[(kb + 2) * 13 + c] + y3 * wc[(kb + 3) * 13 + c];
            for (int o = 16; o; o >>= 1) p += __shfl_down_sync(0xFFFFFFFFu, p, o);
            if (lane == 0) out[n * 13 + c] = p + sbc[c];
        }
    }
}

// ---------------- launch ------------------------------------------------------
extern "C" void kernel_launch(void* const* d_in, const int* in_sizes, int n_in,
                              void* d_out, int out_size) {
    const float* x    = (const float*)d_in[0];
    const int*   ei   = (const int*)d_in[1];
    const float* ea   = (const float*)d_in[2];
    const float* W1   = (const float*)d_in[3];
    const float* We1  = (const float*)d_in[4];
    const float* as1  = (const float*)d_in[5];
    const float* ad1  = (const float*)d_in[6];
    const float* ae1  = (const float*)d_in[7];
    const float* b1   = (const float*)d_in[8];
    const float* gn1w = (const float*)d_in[9];
    const float* gn1b = (const float*)d_in[10];
    const float* gn1m = (const float*)d_in[11];
    const float* W2   = (const float*)d_in[12];
    const float* We2  = (const float*)d_in[13];
    const float* as2  = (const float*)d_in[14];
    const float* ad2  = (const float*)d_in[15];
    const float* ae2  = (const float*)d_in[16];
    const float* b2   = (const float*)d_in[17];
    const float* gn2w = (const float*)d_in[18];
    const float* gn2b = (const float*)d_in[19];
    const float* gn2m = (const float*)d_in[20];
    const float* Wc   = (const float*)d_in[21];
    const float* bc   = (const float*)d_in[22];
    float* out = (float*)d_out;

    float* pB;
    cudaGetSymbolAddress((void**)&pB, g_B);

    cudaFuncSetAttribute(k_gemm2f, cudaFuncAttributeMaxDynamicSharedMemorySize, 256 * XPAD * 4);

    int nb = (NN + 255) / 256;   // 196

    k_cm<<<512, 256>>>(ei, ea);                                        // 1
    k_prep<<<4, 256>>>(We1, ae1, We2, ae2, W1, as1, ad1, W2, as2, ad2);// 2
    k_scan<<<nb, 256>>>(x);                                            // 3
    k_fill<<<(ET / 2 + 255) / 256, 256>>>(ei, ea);                     // 4
    k_gath1z<<<nb, 256>>>();                                           // 5
    k_gemm2f<<<(NN + 63) / 64, 256, 256 * XPAD * 4>>>(W1, W2, b1, gn1m, gn1w, gn1b); // 6
    k_gath2<<<(NN * 32 + 255) / 256, 256>>>();                         // 7
    k_colsum2<<<(NN + 127) / 128, 128>>>(pB, 128);                     // 8
    k_cls<<<512, 256>>>(Wc, bc, b2, gn2m, gn2w, gn2b, out);            // 9
}

// round 11
// speedup vs baseline: 1.5312x; 1.5312x over previous
#include <cuda_runtime.h>
#include <cuda_bf16.h>
#include <math.h>

#define NN 50000
#define EE 400000
#define ET 450000   // EE + NN self loops
#define EPSN 1e-5f
#define XPAD 66     // even -> aligned LDS.64 row pairs

// ---------------- scratch (device globals) -----------------------------------
__device__ float g_A[(size_t)NN * 128];       // h2
__device__ float g_B[(size_t)NN * 128];       // gat2 raw
__device__ float g_Z[(size_t)NN * 16];        // z[d][h][0..2] (float4 per (d,h)), normalized
__device__ float g_alS[(size_t)NN * 4];
__device__ float g_alD[(size_t)NN * 4];
__device__ float g_alS2[(size_t)NN * 2];
__device__ float g_alD2[(size_t)NN * 2];
__device__ float g_colstats[512];             // layer2 sums (self-cleaned in gath1z)
__device__ float g_zmom[36];                  // per head: S0,S1,S2,M00,M01,M02,M11,M12,M22
__device__ float g_eamsum[2];
__device__ float g_eamean[2];
__device__ float g_v1[8];
__device__ float g_v2[4];
__device__ float g_uS1[12], g_uD1[12];
__device__ float g_uS2[512], g_uD2[512];      // [k*2+h]
// CSR (pos-indexed arrays kept SEPARATE: independent chain heads for the gathers)
__device__ int g_cnt[NN];                     // counts (self-cleaned in gath1z)
__device__ int g_rowptr[NN + 1];              // post-fill: rowptr[d] == start of d+1
__device__ int g_csr_src[ET];
__device__ float2 g_csr_ea[ET];               // edge attrs in CSR order (self-loops = mean)

// f32x2 packed helpers
#define FMA2(acc, a, b) asm("fma.rn.f32x2 %0, %1, %2, %0;" : "+l"(acc) : "l"(a), "l"(b))
#define BCAST2(p, f)    asm("mov.b64 %0, {%1, %1};" : "=l"(p) : "f"(f))
#define UNPK2(lo, hi, p) asm("mov.b64 {%0, %1}, %2;" : "=f"(lo), "=f"(hi) : "l"(p))

// ---------------- fused: dst-degree count + edge_attr mean -------------------
__global__ void k_cm(const int* __restrict__ ei, const float* __restrict__ ea) {
    float s0 = 0.f, s1 = 0.f;
    int st = gridDim.x * blockDim.x;
    for (int e = blockIdx.x * blockDim.x + threadIdx.x; e < ET; e += st) {
        int d = (e < EE) ? ei[EE + e] : (e - EE);
        atomicAdd(&g_cnt[d], 1);
        if (e < EE) { s0 += ea[2 * e]; s1 += ea[2 * e + 1]; }
    }
    for (int o = 16; o; o >>= 1) {
        s0 += __shfl_down_sync(0xFFFFFFFFu, s0, o);
        s1 += __shfl_down_sync(0xFFFFFFFFu, s1, o);
    }
    __shared__ float sh[16];
    int lane = threadIdx.x & 31, wid = threadIdx.x >> 5;
    if (lane == 0) { sh[wid] = s0; sh[8 + wid] = s1; }
    __syncthreads();
    if (threadIdx.x == 0) {
        float a = 0.f, b = 0.f;
        for (int w = 0; w < 8; w++) { a += sh[w]; b += sh[8 + w]; }
        atomicAdd(&g_eamsum[0], a);
        atomicAdd(&g_eamsum[1], b);
    }
}

// ---------------- merged precomputes (4 blocks x 256) ------------------------
__global__ void k_prep(const float* __restrict__ We1, const float* __restrict__ ae1,
                       const float* __restrict__ We2, const float* __restrict__ ae2,
                       const float* __restrict__ W1, const float* __restrict__ as1,
                       const float* __restrict__ ad1,
                       const float* __restrict__ W2, const float* __restrict__ as2,
                       const float* __restrict__ ad2) {
    int gt = blockIdx.x * 256 + threadIdx.x;
    {   // uS2/uD2 over all 4 blocks (1024 threads)
        int which = gt >> 9;
        int kk = (gt & 511) >> 1, h = gt & 1;
        const float* a = which ? ad2 : as2;
        float s = 0.f;
        for (int d = 0; d < 64; d++) s += W2[kk * 128 + h * 64 + d] * a[h * 64 + d];
        if (which) g_uD2[kk * 2 + h] = s; else g_uS2[kk * 2 + h] = s;
    }
    if (blockIdx.x != 0) return;
    int t = threadIdx.x;
    if (t < 8) {
        int h = t >> 1, f = t & 1;
        float s = 0.f;
        for (int d = 0; d < 64; d++) s += We1[f * 256 + h * 64 + d] * ae1[h * 64 + d];
        g_v1[t] = s;
    } else if (t < 12) {
        int tt = t - 8, h = tt >> 1, f = tt & 1;
        float s = 0.f;
        for (int d = 0; d < 64; d++) s += We2[f * 128 + h * 64 + d] * ae2[h * 64 + d];
        g_v2[tt] = s;
    } else if (t < 24) {
        int idx = t - 12, f = idx >> 2, h = idx & 3;
        float s = 0.f;
        for (int d = 0; d < 64; d++) s += W1[f * 256 + h * 64 + d] * as1[h * 64 + d];
        g_uS1[idx] = s;
    } else if (t < 36) {
        int idx = t - 24, f = idx >> 2, h = idx & 3;
        float s = 0.f;
        for (int d = 0; d < 64; d++) s += W1[f * 256 + h * 64 + d] * ad1[h * 64 + d];
        g_uD1[idx] = s;
    }
    __syncthreads();
    if (t == 0) {
        g_eamean[0] = g_eamsum[0] / (float)EE;
        g_eamean[1] = g_eamsum[1] / (float)EE;
    }
}

// ---------------- single-kernel scan (+ fused layer1 node logits) ------------
__global__ void k_scan(const float* __restrict__ x) {
    __shared__ int sh[256];
    __shared__ int swr[8];
    int tid = threadIdx.x;
    int i = blockIdx.x * 256 + tid;

    int limit = blockIdx.x << 8;
    int acc = 0;
    for (int t = tid; t < limit; t += 256) acc += g_cnt[t];
    for (int o = 16; o; o >>= 1) acc += __shfl_down_sync(0xFFFFFFFFu, acc, o);
    if ((tid & 31) == 0) swr[tid >> 5] = acc;

    int v = (i < NN) ? g_cnt[i] : 0;
    sh[tid] = v;
    __syncthreads();
    for (int o = 1; o < 256; o <<= 1) {
        int t = (tid >= o) ? sh[tid - o] : 0;
        __syncthreads();
        sh[tid] += t;
        __syncthreads();
    }
    int base = swr[0] + swr[1] + swr[2] + swr[3] + swr[4] + swr[5] + swr[6] + swr[7];
    if (i < NN) g_rowptr[i] = base + sh[tid] - v;   // exclusive start

    // independent: layer1 per-node attention logits
    if (i < NN) {
        float x0 = __ldg(&x[3 * i]), x1 = __ldg(&x[3 * i + 1]), x2 = __ldg(&x[3 * i + 2]);
        float4 s, d;
        s.x = x0 * g_uS1[0] + x1 * g_uS1[4] + x2 * g_uS1[8];
        s.y = x0 * g_uS1[1] + x1 * g_uS1[5] + x2 * g_uS1[9];
        s.z = x0 * g_uS1[2] + x1 * g_uS1[6] + x2 * g_uS1[10];
        s.w = x0 * g_uS1[3] + x1 * g_uS1[7] + x2 * g_uS1[11];
        d.x = x0 * g_uD1[0] + x1 * g_uD1[4] + x2 * g_uD1[8];
        d.y = x0 * g_uD1[1] + x1 * g_uD1[5] + x2 * g_uD1[9];
        d.z = x0 * g_uD1[2] + x1 * g_uD1[6] + x2 * g_uD1[10];
        d.w = x0 * g_uD1[3] + x1 * g_uD1[7] + x2 * g_uD1[11];
        *(float4*)&g_alS[i * 4] = s;
        *(float4*)&g_alD[i * 4] = d;
    }
}

// ---------------- fill: rowptr self-advance, 2 edges/thread ------------------
__global__ void k_fill(const int* __restrict__ ei, const float* __restrict__ ea) {
    int e0 = (blockIdx.x * blockDim.x + threadIdx.x) * 2;
#pragma unroll
    for (int u = 0; u < 2; u++) {
        int e = e0 + u;
        if (e >= ET) break;
        int s, d;
        float2 eav;
        if (e < EE) {
            s = ei[e]; d = ei[EE + e];
            eav = *(const float2*)&ea[2 * e];
        } else {
            s = e - EE; d = s;
            eav = make_float2(g_eamean[0], g_eamean[1]);
        }
        int pos = atomicAdd(&g_rowptr[d], 1);
        g_csr_src[pos] = s;
        g_csr_ea[pos] = eav;
    }
}
// After k_fill: g_rowptr[d] == start of node d+1. Range of d = [d?rowptr[d-1]:0, rowptr[d]).

// ---------------- layer1 gather: thread per node, all 4 heads ----------------
__global__ void __launch_bounds__(256) k_gath1z(const float* __restrict__ x) {
    __shared__ float smom[8][36];
    int n = blockIdx.x * 256 + threadIdx.x;
    if (blockIdx.x == 0) {    // self-clean for later consumers
        g_colstats[threadIdx.x] = 0.f;
        g_colstats[256 + threadIdx.x] = 0.f;
    }
    bool valid = n < NN;
    if (valid) g_cnt[n] = 0;  // ready for next replay's k_cm
    int p0 = 0, p1 = 0;
    if (valid) { p0 = n ? g_rowptr[n - 1] : 0; p1 = g_rowptr[n]; }
    float4 aD = valid ? *(const float4*)&g_alD[n * 4] : make_float4(0.f, 0.f, 0.f, 0.f);
    float v10 = g_v1[0], v11 = g_v1[1], v12 = g_v1[2], v13 = g_v1[3];
    float v14 = g_v1[4], v15 = g_v1[5], v16 = g_v1[6], v17 = g_v1[7];
    float z00 = 0.f, z01 = 0.f, z02 = 0.f, ws0 = 0.f;
    float z10 = 0.f, z11 = 0.f, z12 = 0.f, ws1 = 0.f;
    float z20 = 0.f, z21 = 0.f, z22 = 0.f, ws2 = 0.f;
    float z30 = 0.f, z31 = 0.f, z32 = 0.f, ws3 = 0.f;
#pragma unroll 2
    for (int pos = p0; pos < p1; pos++) {
        int s = __ldg(&g_csr_src[pos]);
        float2 e2 = __ldg(&g_csr_ea[pos]);
        float4 aS = *(const float4*)&g_alS[s * 4];
        float xs0 = __ldg(&x[3 * s]), xs1 = __ldg(&x[3 * s + 1]), xs2 = __ldg(&x[3 * s + 2]);
        float a0 = aS.x + aD.x + e2.x * v10 + e2.y * v11;
        float a1 = aS.y + aD.y + e2.x * v12 + e2.y * v13;
        float a2 = aS.z + aD.z + e2.x * v14 + e2.y * v15;
        float a3 = aS.w + aD.w + e2.x * v16 + e2.y * v17;
        a0 = a0 > 0.f ? a0 : 0.2f * a0;
        a1 = a1 > 0.f ? a1 : 0.2f * a1;
        a2 = a2 > 0.f ? a2 : 0.2f * a2;
        a3 = a3 > 0.f ? a3 : 0.2f * a3;
        float w0 = __expf(a0), w1 = __expf(a1), w2 = __expf(a2), w3 = __expf(a3);
        ws0 += w0; z00 += w0 * xs0; z01 += w0 * xs1; z02 += w0 * xs2;
        ws1 += w1; z10 += w1 * xs0; z11 += w1 * xs1; z12 += w1 * xs2;
        ws2 += w2; z20 += w2 * xs0; z21 += w2 * xs1; z22 += w2 * xs2;
        ws3 += w3; z30 += w3 * xs0; z31 += w3 * xs1; z32 += w3 * xs2;
    }
    float r;
    r = valid ? 1.f / ws0 : 0.f; z00 *= r; z01 *= r; z02 *= r;
    r = valid ? 1.f / ws1 : 0.f; z10 *= r; z11 *= r; z12 *= r;
    r = valid ? 1.f / ws2 : 0.f; z20 *= r; z21 *= r; z22 *= r;
    r = valid ? 1.f / ws3 : 0.f; z30 *= r; z31 *= r; z32 *= r;
    if (valid) {
        *(float4*)&g_Z[(size_t)n * 16 + 0]  = make_float4(z00, z01, z02, 0.f);
        *(float4*)&g_Z[(size_t)n * 16 + 4]  = make_float4(z10, z11, z12, 0.f);
        *(float4*)&g_Z[(size_t)n * 16 + 8]  = make_float4(z20, z21, z22, 0.f);
        *(float4*)&g_Z[(size_t)n * 16 + 12] = make_float4(z30, z31, z32, 0.f);
    }

    // per-head moments: warp reduce, block reduce, 36 atomics/block
    int lane = threadIdx.x & 31, wi = threadIdx.x >> 5;
    float zz[4][3] = {{z00, z01, z02}, {z10, z11, z12}, {z20, z21, z22}, {z30, z31, z32}};
#pragma unroll
    for (int h = 0; h < 4; h++) {
        float a = zz[h][0], b = zz[h][1], cq = zz[h][2];
        float p[9] = {a, b, cq, a * a, a * b, a * cq, b * b, b * cq, cq * cq};
#pragma unroll
        for (int i = 0; i < 9; i++) {
            float v = p[i];
            v += __shfl_down_sync(0xFFFFFFFFu, v, 16);
            v += __shfl_down_sync(0xFFFFFFFFu, v, 8);
            v += __shfl_down_sync(0xFFFFFFFFu, v, 4);
            v += __shfl_down_sync(0xFFFFFFFFu, v, 2);
            v += __shfl_down_sync(0xFFFFFFFFu, v, 1);
            p[i] = v;
        }
        if (lane == 0) {
#pragma unroll
            for (int i = 0; i < 9; i++) smom[wi][h * 9 + i] = p[i];
        }
    }
    __syncthreads();
    if (threadIdx.x < 36) {
        float s = 0.f;
#pragma unroll
        for (int w = 0; w < 8; w++) s += smom[w][threadIdx.x];
        atomicAdd(&g_zmom[threadIdx.x], s);
    }
}

// ---------------- fused GEMM2: inline layer1 norm, z-expand, f32x2 FMA -------
__global__ void __launch_bounds__(256) k_gemm2f(const float* __restrict__ W1,
                                                const float* __restrict__ W2,
                                                const float* __restrict__ b1,
                                                const float* __restrict__ ms1,
                                                const float* __restrict__ gw1,
                                                const float* __restrict__ gb1) {
    extern __shared__ float xs[];          // [256][XPAD] k-major
    __shared__ float cs[256], cf[256], us[512], ud[512], w1s[768], zs[64 * 16];
    __shared__ float zm[36];
    int tid = threadIdx.x;
    us[tid] = g_uS2[tid]; us[256 + tid] = g_uS2[256 + tid];
    ud[tid] = g_uD2[tid]; ud[256 + tid] = g_uD2[256 + tid];
    w1s[tid] = W1[tid]; w1s[256 + tid] = W1[256 + tid]; w1s[512 + tid] = W1[512 + tid];
    if (tid < 36) zm[tid] = g_zmom[tid];

    int r0 = blockIdx.x * 64;
    {   // stage z rows: 64 nodes x 4 float4
        int row = tid >> 2, part = tid & 3;
        float4 zv = make_float4(0.f, 0.f, 0.f, 0.f);
        if (r0 + row < NN) zv = *(const float4*)&g_Z[(size_t)(r0 + row) * 16 + part * 4];
        *(float4*)&zs[(row * 4 + part) * 4] = zv;
    }
    __syncthreads();

    {   // inline layer-1 GraphNorm coefficients from z-moments
        int j = tid, h = j >> 6;
        float w0 = w1s[j], w1 = w1s[256 + j], w2 = w1s[512 + j];
        const float* m = zm + h * 9;
        float sum = w0 * m[0] + w1 * m[1] + w2 * m[2];
        float sq  = w0 * w0 * m[3] + w1 * w1 * m[6] + w2 * w2 * m[8]
                  + 2.f * (w0 * w1 * m[4] + w0 * w2 * m[5] + w1 * w2 * m[7]);
        float invN = 1.0f / NN;
        float bj = b1[j];
        float mean = sum * invN + bj;
        float cp = bj - mean * ms1[j];
        float var = sq * invN + 2.f * cp * (sum * invN) + cp * cp;
        float rstd = rsqrtf(var + EPSN);
        cs[j] = gw1[j] * rstd;
        cf[j] = cp * gw1[j] * rstd + gb1[j];
    }
    __syncthreads();

    // expand + norm + ELU into xs (k-major, transposed)
    for (int idx = tid; idx < 64 * 64; idx += 256) {
        int r = idx >> 6, kq = idx & 63;
        int k4 = kq * 4, h = kq >> 4;
        const float* zp = zs + (r * 4 + h) * 4;
        float z0 = zp[0], z1 = zp[1], z2 = zp[2];
#pragma unroll
        for (int cc = 0; cc < 4; cc++) {
            int c = k4 + cc;
            float v = z0 * w1s[c] + z1 * w1s[256 + c] + z2 * w1s[512 + c];
            float y = v * cs[c] + cf[c];
            y = y > 0.f ? y : expm1f(y);
            xs[c * XPAD + r] = y;
        }
    }
    __syncthreads();

    int tx = tid & 31, ty = tid >> 5;
    int c0 = tx * 4, rb = ty * 8;
    unsigned long long acc[4][4];
#pragma unroll
    for (int p = 0; p < 4; p++)
#pragma unroll
        for (int c = 0; c < 4; c++) acc[p][c] = 0ull;

    const float* W2p = W2 + c0;
#pragma unroll 4
    for (int k = 0; k < 256; k++) {
        const unsigned long long* xq = (const unsigned long long*)(xs + k * XPAD + rb);
        float4 w = __ldg((const float4*)(W2p + k * 128));
        unsigned long long xp0 = xq[0], xp1 = xq[1], xp2 = xq[2], xp3 = xq[3];
        unsigned long long wp;
        BCAST2(wp, w.x);
        FMA2(acc[0][0], xp0, wp); FMA2(acc[1][0], xp1, wp); FMA2(acc[2][0], xp2, wp); FMA2(acc[3][0], xp3, wp);
        BCAST2(wp, w.y);
        FMA2(acc[0][1], xp0, wp); FMA2(acc[1][1], xp1, wp); FMA2(acc[2][1], xp2, wp); FMA2(acc[3][1], xp3, wp);
        BCAST2(wp, w.z);
        FMA2(acc[0][2], xp0, wp); FMA2(acc[1][2], xp1, wp); FMA2(acc[2][2], xp2, wp); FMA2(acc[3][2], xp3, wp);
        BCAST2(wp, w.w);
        FMA2(acc[0][3], xp0, wp); FMA2(acc[1][3], xp1, wp); FMA2(acc[2][3], xp2, wp); FMA2(acc[3][3], xp3, wp);
    }

#pragma unroll
    for (int p = 0; p < 4; p++) {
        int row = r0 + rb + 2 * p;
        float l0, h0, l1, h1, l2, h2v, l3, h3;
        UNPK2(l0, h0, acc[p][0]);
        UNPK2(l1, h1, acc[p][1]);
        UNPK2(l2, h2v, acc[p][2]);
        UNPK2(l3, h3, acc[p][3]);
        if (row < NN)     *(float4*)(g_A + (size_t)row * 128 + c0)       = make_float4(l0, l1, l2, l3);
        if (row + 1 < NN) *(float4*)(g_A + (size_t)(row + 1) * 128 + c0) = make_float4(h0, h1, h2v, h3);
    }

    {   // layer-2 attention logits from the normalized tile
        int row = tid >> 2, q = tid & 3;
        int grow = r0 + row;
        const float* uu = (q < 2) ? (us + q) : (ud + (q - 2));
        float s = 0.f;
#pragma unroll 8
        for (int k = 0; k < 256; k++)
            s += xs[k * XPAD + row] * uu[k * 2];
        if (grow < NN) {
            if (q < 2) g_alS2[grow * 2 + q] = s;
            else       g_alD2[grow * 2 + (q - 2)] = s;
        }
    }
}

// ---------------- layer2 gather: warp per node, fused alpha, plain loop ------
__global__ void __launch_bounds__(256) k_gath2() {
    if (blockIdx.x == 0) {   // self-clean for next replay
        if (threadIdx.x < 36) g_zmom[threadIdx.x] = 0.f;
        if (threadIdx.x >= 36 && threadIdx.x < 38) g_eamsum[threadIdx.x - 36] = 0.f;
    }
    int d = (blockIdx.x * 256 + threadIdx.x) >> 5;
    if (d >= NN) return;
    int lane = threadIdx.x & 31;
    int j = lane * 4;
    int h = lane >> 4;
    int p0 = d ? g_rowptr[d - 1] : 0;
    int p1 = g_rowptr[d];
    float v20 = g_v2[2 * h], v21 = g_v2[2 * h + 1];
    float aD = g_alD2[d * 2 + h];
    float4 acc = make_float4(0.f, 0.f, 0.f, 0.f);
    float ws = 0.f;
#pragma unroll 2
    for (int pos = p0; pos < p1; pos++) {
        int s = __ldg(&g_csr_src[pos]);
        float2 e2 = __ldg(&g_csr_ea[pos]);
        float a = __ldg(&g_alS2[s * 2 + h]) + aD + e2.x * v20 + e2.y * v21;
        a = a > 0.f ? a : 0.2f * a;
        float w = __expf(a);
        float4 v = *(const float4*)(g_A + (size_t)s * 128 + j);
        ws += w;
        acc.x += v.x * w; acc.y += v.y * w; acc.z += v.z * w; acc.w += v.w * w;
    }
    float r = 1.f / ws;
    acc.x *= r; acc.y *= r; acc.z *= r; acc.w *= r;
    *(float4*)(g_B + (size_t)d * 128 + j) = acc;
}

// ---------------- layer2 GraphNorm column stats ------------------------------
__global__ void k_colsum2(const float* __restrict__ X, int rpb) {
    int j = threadIdx.x;   // 128
    int r0 = blockIdx.x * rpb, r1 = min(r0 + rpb, NN);
    float s = 0.f, q = 0.f;
    for (int r = r0; r < r1; r++) {
        float v = X[(size_t)r * 128 + j];
        s += v;
        q += v * v;
    }
    atomicAdd(&g_colstats[j], s);
    atomicAdd(&g_colstats[256 + j], q);
}

// ---------------- classifier (inline layer2 norm + ELU) ----------------------
__global__ void k_cls(const float* __restrict__ Wc, const float* __restrict__ bc,
                      const float* __restrict__ b2, const float* __restrict__ ms2,
                      const float* __restrict__ gw2, const float* __restrict__ gb2,
                      float* __restrict__ out) {
    __shared__ float wc[128 * 13];
    __shared__ float sbc[13];
    __shared__ float cs[128], cf[128];
    for (int i = threadIdx.x; i < 128 * 13; i += 256) wc[i] = Wc[i];
    if (threadIdx.x < 13) sbc[threadIdx.x] = bc[threadIdx.x];
    if (threadIdx.x < 128) {
        int j = threadIdx.x;
        float invN = 1.0f / NN;
        float sum = g_colstats[j], sq = g_colstats[256 + j];
        float bj = b2[j];
        float m = sum * invN + bj;
        float cp = bj - m * ms2[j];
        float var = sq * invN + 2.f * cp * (sum * invN) + cp * cp;
        float rstd = rsqrtf(var + EPSN);
        cs[j] = gw2[j] * rstd;
        cf[j] = cp * gw2[j] * rstd + gb2[j];
    }
    __syncthreads();
    int warp = (blockIdx.x * 256 + threadIdx.x) >> 5;
    int lane = threadIdx.x & 31;
    int nw = (gridDim.x * 256) >> 5;
    for (int n = warp; n < NN; n += nw) {
        float4 hv = *(const float4*)(g_B + (size_t)n * 128 + lane * 4);
        int kb = lane * 4;
        float y0 = hv.x * cs[kb + 0] + cf[kb + 0]; y0 = y0 > 0.f ? y0 : expm1f(y0);
        float y1 = hv.y * cs[kb + 1] + cf[kb + 1]; y1 = y1 > 0.f ? y1 : expm1f(y1);
        float y2 = hv.z * cs[kb + 2] + cf[kb + 2]; y2 = y2 > 0.f ? y2 : expm1f(y2);
        float y3 = hv.w * cs[kb + 3] + cf[kb + 3]; y3 = y3 > 0.f ? y3 : expm1f(y3);
#pragma unroll
        for (int c = 0; c < 13; c++) {
            float p = y0 * wc[kb * 13 + c] + y1 * wc[(kb + 1) * 13 + c]
                    + y2 * wc[(kb + 2) * 13 + c] + y3 * wc[(kb + 3) * 13 + c];
            for (int o = 16; o; o >>= 1) p += __shfl_down_sync(0xFFFFFFFFu, p, o);
            if (lane == 0) out[n * 13 + c] = p + sbc[c];
        }
    }
}

// ---------------- launch ------------------------------------------------------
extern "C" void kernel_launch(void* const* d_in, const int* in_sizes, int n_in,
                              void* d_out, int out_size) {
    const float* x    = (const float*)d_in[0];
    const int*   ei   = (const int*)d_in[1];
    const float* ea   = (const float*)d_in[2];
    const float* W1   = (const float*)d_in[3];
    const float* We1  = (const float*)d_in[4];
    const float* as1  = (const float*)d_in[5];
    const float* ad1  = (const float*)d_in[6];
    const float* ae1  = (const float*)d_in[7];
    const float* b1   = (const float*)d_in[8];
    const float* gn1w = (const float*)d_in[9];
    const float* gn1b = (const float*)d_in[10];
    const float* gn1m = (const float*)d_in[11];
    const float* W2   = (const float*)d_in[12];
    const float* We2  = (const float*)d_in[13];
    const float* as2  = (const float*)d_in[14];
    const float* ad2  = (const float*)d_in[15];
    const float* ae2  = (const float*)d_in[16];
    const float* b2   = (const float*)d_in[17];
    const float* gn2w = (const float*)d_in[18];
    const float* gn2b = (const float*)d_in[19];
    const float* gn2m = (const float*)d_in[20];
    const float* Wc   = (const float*)d_in[21];
    const float* bc   = (const float*)d_in[22];
    float* out = (float*)d_out;

    float* pB;
    cudaGetSymbolAddress((void**)&pB, g_B);

    cudaFuncSetAttribute(k_gemm2f, cudaFuncAttributeMaxDynamicSharedMemorySize, 256 * XPAD * 4);

    int nb = (NN + 255) / 256;   // 196

    k_cm<<<512, 256>>>(ei, ea);                                        // 1
    k_prep<<<4, 256>>>(We1, ae1, We2, ae2, W1, as1, ad1, W2, as2, ad2);// 2
    k_scan<<<nb, 256>>>(x);                                            // 3
    k_fill<<<(ET / 2 + 255) / 256, 256>>>(ei, ea);                     // 4
    k_gath1z<<<nb, 256>>>(x);                                          // 5
    k_gemm2f<<<(NN + 63) / 64, 256, 256 * XPAD * 4>>>(W1, W2, b1, gn1m, gn1w, gn1b); // 6
    k_gath2<<<(NN * 32 + 255) / 256, 256>>>();                         // 7
    k_colsum2<<<(NN + 127) / 128, 128>>>(pB, 128);                     // 8
    k_cls<<<512, 256>>>(Wc, bc, b2, gn2m, gn2w, gn2b, out);            // 9
}

// round 14
// speedup vs baseline: 1.6109x; 1.0521x over previous
#include <cuda_runtime.h>
#include <cuda_bf16.h>
#include <math.h>

#define NN 50000
#define EE 400000
#define ET 450000   // EE + NN self loops
#define EPSN 1e-5f
#define XPAD 66     // even -> aligned LDS.64 row pairs

// ---------------- scratch (device globals) -----------------------------------
__device__ float g_A[(size_t)NN * 128];       // h2
__device__ float g_B[(size_t)NN * 128];       // gat2 raw
__device__ float g_Z[(size_t)NN * 16];        // z[d][h][0..2] (float4 per (d,h)), normalized
__device__ float g_alS[(size_t)NN * 4];
__device__ float g_alD[(size_t)NN * 4];
__device__ float g_alS2[(size_t)NN * 2];
__device__ float g_alD2[(size_t)NN * 2];
__device__ float g_colstats[512];             // layer2 sums (self-cleaned in gath1z)
__device__ float g_zmom[36];                  // per head: S0,S1,S2,M00,M01,M02,M11,M12,M22
__device__ float g_eamsum[2];
__device__ float g_eamean[2];
__device__ float g_v1[8];
__device__ float g_v2[4];
__device__ float g_uS1[12], g_uD1[12];
__device__ float g_uS2[512], g_uD2[512];      // [k*2+h]
// CSR (pos-indexed arrays kept SEPARATE: independent chain heads for the gathers)
__device__ int g_cnt[NN];                     // counts (self-cleaned in gath1z)
__device__ int g_rowptr[NN + 1];              // post-fill: rowptr[d] == start of d+1
__device__ int g_csr_src[ET];
__device__ float2 g_csr_ea[ET];               // edge attrs in CSR order (self-loops = mean)

// f32x2 packed helpers
#define FMA2(acc, a, b) asm("fma.rn.f32x2 %0, %1, %2, %0;" : "+l"(acc) : "l"(a), "l"(b))
#define BCAST2(p, f)    asm("mov.b64 %0, {%1, %1};" : "=l"(p) : "f"(f))
#define UNPK2(lo, hi, p) asm("mov.b64 {%0, %1}, %2;" : "=f"(lo), "=f"(hi) : "l"(p))

// ---------------- merged: weight precomputes + degree count + ea mean --------
// blocks 0..3: uS2/uD2 (+ block 0: v1/v2/uS1/uD1). blocks >=4: edge loop.
__global__ void k_prepcm(const int* __restrict__ ei, const float* __restrict__ ea,
                         const float* __restrict__ We1, const float* __restrict__ ae1,
                         const float* __restrict__ We2, const float* __restrict__ ae2,
                         const float* __restrict__ W1, const float* __restrict__ as1,
                         const float* __restrict__ ad1,
                         const float* __restrict__ W2, const float* __restrict__ as2,
                         const float* __restrict__ ad2) {
    if (blockIdx.x >= 4) {
        // ---- cm part: dst-degree count + edge_attr sum ----
        int b = blockIdx.x - 4;
        int nb = gridDim.x - 4;
        float s0 = 0.f, s1 = 0.f;
        int st = nb * 256;
        for (int e = b * 256 + threadIdx.x; e < ET; e += st) {
            int d = (e < EE) ? ei[EE + e] : (e - EE);
            atomicAdd(&g_cnt[d], 1);
            if (e < EE) { s0 += ea[2 * e]; s1 += ea[2 * e + 1]; }
        }
        for (int o = 16; o; o >>= 1) {
            s0 += __shfl_down_sync(0xFFFFFFFFu, s0, o);
            s1 += __shfl_down_sync(0xFFFFFFFFu, s1, o);
        }
        __shared__ float sh[16];
        int lane = threadIdx.x & 31, wid = threadIdx.x >> 5;
        if (lane == 0) { sh[wid] = s0; sh[8 + wid] = s1; }
        __syncthreads();
        if (threadIdx.x == 0) {
            float a = 0.f, b2 = 0.f;
            for (int w = 0; w < 8; w++) { a += sh[w]; b2 += sh[8 + w]; }
            atomicAdd(&g_eamsum[0], a);
            atomicAdd(&g_eamsum[1], b2);
        }
        return;
    }
    // ---- prep part ----
    int gt = blockIdx.x * 256 + threadIdx.x;   // 0..1023
    {
        int which = gt >> 9;
        int kk = (gt & 511) >> 1, h = gt & 1;
        const float* a = which ? ad2 : as2;
        float s = 0.f;
        for (int d = 0; d < 64; d++) s += W2[kk * 128 + h * 64 + d] * a[h * 64 + d];
        if (which) g_uD2[kk * 2 + h] = s; else g_uS2[kk * 2 + h] = s;
    }
    if (blockIdx.x != 0) return;
    int t = threadIdx.x;
    if (t < 8) {
        int h = t >> 1, f = t & 1;
        float s = 0.f;
        for (int d = 0; d < 64; d++) s += We1[f * 256 + h * 64 + d] * ae1[h * 64 + d];
        g_v1[t] = s;
    } else if (t < 12) {
        int tt = t - 8, h = tt >> 1, f = tt & 1;
        float s = 0.f;
        for (int d = 0; d < 64; d++) s += We2[f * 128 + h * 64 + d] * ae2[h * 64 + d];
        g_v2[tt] = s;
    } else if (t < 24) {
        int idx = t - 12, f = idx >> 2, h = idx & 3;
        float s = 0.f;
        for (int d = 0; d < 64; d++) s += W1[f * 256 + h * 64 + d] * as1[h * 64 + d];
        g_uS1[idx] = s;
    } else if (t < 36) {
        int idx = t - 24, f = idx >> 2, h = idx & 3;
        float s = 0.f;
        for (int d = 0; d < 64; d++) s += W1[f * 256 + h * 64 + d] * ad1[h * 64 + d];
        g_uD1[idx] = s;
    }
}

// ---------------- single-kernel scan (+ layer1 node logits + eamean) ---------
__global__ void k_scan(const float* __restrict__ x) {
    __shared__ int sh[256];
    __shared__ int swr[8];
    int tid = threadIdx.x;
    int i = blockIdx.x * 256 + tid;

    if (blockIdx.x == 0 && tid == 0) {   // finalize edge-attr mean (for k_fill)
        g_eamean[0] = g_eamsum[0] / (float)EE;
        g_eamean[1] = g_eamsum[1] / (float)EE;
    }

    int limit = blockIdx.x << 8;
    int acc = 0;
    for (int t = tid; t < limit; t += 256) acc += g_cnt[t];
    for (int o = 16; o; o >>= 1) acc += __shfl_down_sync(0xFFFFFFFFu, acc, o);
    if ((tid & 31) == 0) swr[tid >> 5] = acc;

    int v = (i < NN) ? g_cnt[i] : 0;
    sh[tid] = v;
    __syncthreads();
    for (int o = 1; o < 256; o <<= 1) {
        int t = (tid >= o) ? sh[tid - o] : 0;
        __syncthreads();
        sh[tid] += t;
        __syncthreads();
    }
    int base = swr[0] + swr[1] + swr[2] + swr[3] + swr[4] + swr[5] + swr[6] + swr[7];
    if (i < NN) g_rowptr[i] = base + sh[tid] - v;   // exclusive start

    // independent: layer1 per-node attention logits
    if (i < NN) {
        float x0 = __ldg(&x[3 * i]), x1 = __ldg(&x[3 * i + 1]), x2 = __ldg(&x[3 * i + 2]);
        float4 s, d;
        s.x = x0 * g_uS1[0] + x1 * g_uS1[4] + x2 * g_uS1[8];
        s.y = x0 * g_uS1[1] + x1 * g_uS1[5] + x2 * g_uS1[9];
        s.z = x0 * g_uS1[2] + x1 * g_uS1[6] + x2 * g_uS1[10];
        s.w = x0 * g_uS1[3] + x1 * g_uS1[7] + x2 * g_uS1[11];
        d.x = x0 * g_uD1[0] + x1 * g_uD1[4] + x2 * g_uD1[8];
        d.y = x0 * g_uD1[1] + x1 * g_uD1[5] + x2 * g_uD1[9];
        d.z = x0 * g_uD1[2] + x1 * g_uD1[6] + x2 * g_uD1[10];
        d.w = x0 * g_uD1[3] + x1 * g_uD1[7] + x2 * g_uD1[11];
        *(float4*)&g_alS[i * 4] = s;
        *(float4*)&g_alD[i * 4] = d;
    }
}

// ---------------- fill: rowptr self-advance, 4 edges/thread ------------------
__global__ void k_fill(const int* __restrict__ ei, const float* __restrict__ ea) {
    int e0 = (blockIdx.x * blockDim.x + threadIdx.x) * 4;
#pragma unroll
    for (int u = 0; u < 4; u++) {
        int e = e0 + u;
        if (e >= ET) break;
        int s, d;
        float2 eav;
        if (e < EE) {
            s = ei[e]; d = ei[EE + e];
            eav = *(const float2*)&ea[2 * e];
        } else {
            s = e - EE; d = s;
            eav = make_float2(g_eamean[0], g_eamean[1]);
        }
        int pos = atomicAdd(&g_rowptr[d], 1);
        g_csr_src[pos] = s;
        g_csr_ea[pos] = eav;
    }
}
// After k_fill: g_rowptr[d] == start of node d+1. Range of d = [d?rowptr[d-1]:0, rowptr[d]).

// ---------------- layer1 gather: thread per node, all 4 heads ----------------
__global__ void __launch_bounds__(256) k_gath1z(const float* __restrict__ x) {
    __shared__ float smom[8][36];
    int n = blockIdx.x * 256 + threadIdx.x;
    if (blockIdx.x == 0) {    // self-clean for later consumers
        g_colstats[threadIdx.x] = 0.f;
        g_colstats[256 + threadIdx.x] = 0.f;
    }
    bool valid = n < NN;
    if (valid) g_cnt[n] = 0;  // ready for next replay's k_prepcm
    int p0 = 0, p1 = 0;
    if (valid) { p0 = n ? g_rowptr[n - 1] : 0; p1 = g_rowptr[n]; }
    float4 aD = valid ? *(const float4*)&g_alD[n * 4] : make_float4(0.f, 0.f, 0.f, 0.f);
    float v10 = g_v1[0], v11 = g_v1[1], v12 = g_v1[2], v13 = g_v1[3];
    float v14 = g_v1[4], v15 = g_v1[5], v16 = g_v1[6], v17 = g_v1[7];
    float z00 = 0.f, z01 = 0.f, z02 = 0.f, ws0 = 0.f;
    float z10 = 0.f, z11 = 0.f, z12 = 0.f, ws1 = 0.f;
    float z20 = 0.f, z21 = 0.f, z22 = 0.f, ws2 = 0.f;
    float z30 = 0.f, z31 = 0.f, z32 = 0.f, ws3 = 0.f;
#pragma unroll 2
    for (int pos = p0; pos < p1; pos++) {
        int s = __ldg(&g_csr_src[pos]);
        float2 e2 = __ldg(&g_csr_ea[pos]);
        float4 aS = *(const float4*)&g_alS[s * 4];
        float xs0 = __ldg(&x[3 * s]), xs1 = __ldg(&x[3 * s + 1]), xs2 = __ldg(&x[3 * s + 2]);
        float a0 = aS.x + aD.x + e2.x * v10 + e2.y * v11;
        float a1 = aS.y + aD.y + e2.x * v12 + e2.y * v13;
        float a2 = aS.z + aD.z + e2.x * v14 + e2.y * v15;
        float a3 = aS.w + aD.w + e2.x * v16 + e2.y * v17;
        a0 = a0 > 0.f ? a0 : 0.2f * a0;
        a1 = a1 > 0.f ? a1 : 0.2f * a1;
        a2 = a2 > 0.f ? a2 : 0.2f * a2;
        a3 = a3 > 0.f ? a3 : 0.2f * a3;
        float w0 = __expf(a0), w1 = __expf(a1), w2 = __expf(a2), w3 = __expf(a3);
        ws0 += w0; z00 += w0 * xs0; z01 += w0 * xs1; z02 += w0 * xs2;
        ws1 += w1; z10 += w1 * xs0; z11 += w1 * xs1; z12 += w1 * xs2;
        ws2 += w2; z20 += w2 * xs0; z21 += w2 * xs1; z22 += w2 * xs2;
        ws3 += w3; z30 += w3 * xs0; z31 += w3 * xs1; z32 += w3 * xs2;
    }
    float r;
    r = valid ? 1.f / ws0 : 0.f; z00 *= r; z01 *= r; z02 *= r;
    r = valid ? 1.f / ws1 : 0.f; z10 *= r; z11 *= r; z12 *= r;
    r = valid ? 1.f / ws2 : 0.f; z20 *= r; z21 *= r; z22 *= r;
    r = valid ? 1.f / ws3 : 0.f; z30 *= r; z31 *= r; z32 *= r;
    if (valid) {
        *(float4*)&g_Z[(size_t)n * 16 + 0]  = make_float4(z00, z01, z02, 0.f);
        *(float4*)&g_Z[(size_t)n * 16 + 4]  = make_float4(z10, z11, z12, 0.f);
        *(float4*)&g_Z[(size_t)n * 16 + 8]  = make_float4(z20, z21, z22, 0.f);
        *(float4*)&g_Z[(size_t)n * 16 + 12] = make_float4(z30, z31, z32, 0.f);
    }

    // per-head moments: warp reduce, block reduce, 36 atomics/block
    int lane = threadIdx.x & 31, wi = threadIdx.x >> 5;
    float zz[4][3] = {{z00, z01, z02}, {z10, z11, z12}, {z20, z21, z22}, {z30, z31, z32}};
#pragma unroll
    for (int h = 0; h < 4; h++) {
        float a = zz[h][0], b = zz[h][1], cq = zz[h][2];
        float p[9] = {a, b, cq, a * a, a * b, a * cq, b * b, b * cq, cq * cq};
#pragma unroll
        for (int i = 0; i < 9; i++) {
            float v = p[i];
            v += __shfl_down_sync(0xFFFFFFFFu, v, 16);
            v += __shfl_down_sync(0xFFFFFFFFu, v, 8);
            v += __shfl_down_sync(0xFFFFFFFFu, v, 4);
            v += __shfl_down_sync(0xFFFFFFFFu, v, 2);
            v += __shfl_down_sync(0xFFFFFFFFu, v, 1);
            p[i] = v;
        }
        if (lane == 0) {
#pragma unroll
            for (int i = 0; i < 9; i++) smom[wi][h * 9 + i] = p[i];
        }
    }
    __syncthreads();
    if (threadIdx.x < 36) {
        float s = 0.f;
#pragma unroll
        for (int w = 0; w < 8; w++) s += smom[w][threadIdx.x];
        atomicAdd(&g_zmom[threadIdx.x], s);
    }
}

// ---------------- fused GEMM2: inline layer1 norm, z-expand, f32x2 FMA -------
__global__ void __launch_bounds__(256) k_gemm2f(const float* __restrict__ W1,
                                                const float* __restrict__ W2,
                                                const float* __restrict__ b1,
                                                const float* __restrict__ ms1,
                                                const float* __restrict__ gw1,
                                                const float* __restrict__ gb1) {
    extern __shared__ float xs[];          // [256][XPAD] k-major
    __shared__ float cs[256], cf[256], us[512], ud[512], w1s[768], zs[64 * 16];
    __shared__ float zm[36];
    int tid = threadIdx.x;
    us[tid] = g_uS2[tid]; us[256 + tid] = g_uS2[256 + tid];
    ud[tid] = g_uD2[tid]; ud[256 + tid] = g_uD2[256 + tid];
    w1s[tid] = W1[tid]; w1s[256 + tid] = W1[256 + tid]; w1s[512 + tid] = W1[512 + tid];
    if (tid < 36) zm[tid] = g_zmom[tid];

    int r0 = blockIdx.x * 64;
    {   // stage z rows: 64 nodes x 4 float4
        int row = tid >> 2, part = tid & 3;
        float4 zv = make_float4(0.f, 0.f, 0.f, 0.f);
        if (r0 + row < NN) zv = *(const float4*)&g_Z[(size_t)(r0 + row) * 16 + part * 4];
        *(float4*)&zs[(row * 4 + part) * 4] = zv;
    }
    __syncthreads();

    {   // inline layer-1 GraphNorm coefficients from z-moments
        int j = tid, h = j >> 6;
        float w0 = w1s[j], w1 = w1s[256 + j], w2 = w1s[512 + j];
        const float* m = zm + h * 9;
        float sum = w0 * m[0] + w1 * m[1] + w2 * m[2];
        float sq  = w0 * w0 * m[3] + w1 * w1 * m[6] + w2 * w2 * m[8]
                  + 2.f * (w0 * w1 * m[4] + w0 * w2 * m[5] + w1 * w2 * m[7]);
        float invN = 1.0f / NN;
        float bj = b1[j];
        float mean = sum * invN + bj;
        float cp = bj - mean * ms1[j];
        float var = sq * invN + 2.f * cp * (sum * invN) + cp * cp;
        float rstd = rsqrtf(var + EPSN);
        cs[j] = gw1[j] * rstd;
        cf[j] = cp * gw1[j] * rstd + gb1[j];
    }
    __syncthreads();

    // expand + norm + ELU into xs (k-major, transposed)
    for (int idx = tid; idx < 64 * 64; idx += 256) {
        int r = idx >> 6, kq = idx & 63;
        int k4 = kq * 4, h = kq >> 4;
        const float* zp = zs + (r * 4 + h) * 4;
        float z0 = zp[0], z1 = zp[1], z2 = zp[2];
#pragma unroll
        for (int cc = 0; cc < 4; cc++) {
            int c = k4 + cc;
            float v = z0 * w1s[c] + z1 * w1s[256 + c] + z2 * w1s[512 + c];
            float y = v * cs[c] + cf[c];
            y = y > 0.f ? y : expm1f(y);
            xs[c * XPAD + r] = y;
        }
    }
    __syncthreads();

    int tx = tid & 31, ty = tid >> 5;
    int c0 = tx * 4, rb = ty * 8;
    unsigned long long acc[4][4];
#pragma unroll
    for (int p = 0; p < 4; p++)
#pragma unroll
        for (int c = 0; c < 4; c++) acc[p][c] = 0ull;

    const float* W2p = W2 + c0;
#pragma unroll 4
    for (int k = 0; k < 256; k++) {
        const unsigned long long* xq = (const unsigned long long*)(xs + k * XPAD + rb);
        float4 w = __ldg((const float4*)(W2p + k * 128));
        unsigned long long xp0 = xq[0], xp1 = xq[1], xp2 = xq[2], xp3 = xq[3];
        unsigned long long wp;
        BCAST2(wp, w.x);
        FMA2(acc[0][0], xp0, wp); FMA2(acc[1][0], xp1, wp); FMA2(acc[2][0], xp2, wp); FMA2(acc[3][0], xp3, wp);
        BCAST2(wp, w.y);
        FMA2(acc[0][1], xp0, wp); FMA2(acc[1][1], xp1, wp); FMA2(acc[2][1], xp2, wp); FMA2(acc[3][1], xp3, wp);
        BCAST2(wp, w.z);
        FMA2(acc[0][2], xp0, wp); FMA2(acc[1][2], xp1, wp); FMA2(acc[2][2], xp2, wp); FMA2(acc[3][2], xp3, wp);
        BCAST2(wp, w.w);
        FMA2(acc[0][3], xp0, wp); FMA2(acc[1][3], xp1, wp); FMA2(acc[2][3], xp2, wp); FMA2(acc[3][3], xp3, wp);
    }

#pragma unroll
    for (int p = 0; p < 4; p++) {
        int row = r0 + rb + 2 * p;
        float l0, h0, l1, h1, l2, h2v, l3, h3;
        UNPK2(l0, h0, acc[p][0]);
        UNPK2(l1, h1, acc[p][1]);
        UNPK2(l2, h2v, acc[p][2]);
        UNPK2(l3, h3, acc[p][3]);
        if (row < NN)     *(float4*)(g_A + (size_t)row * 128 + c0)       = make_float4(l0, l1, l2, l3);
        if (row + 1 < NN) *(float4*)(g_A + (size_t)(row + 1) * 128 + c0) = make_float4(h0, h1, h2v, h3);
    }

    {   // layer-2 attention logits from the normalized tile
        int row = tid >> 2, q = tid & 3;
        int grow = r0 + row;
        const float* uu = (q < 2) ? (us + q) : (ud + (q - 2));
        float s = 0.f;
#pragma unroll 8
        for (int k = 0; k < 256; k++)
            s += xs[k * XPAD + row] * uu[k * 2];
        if (grow < NN) {
            if (q < 2) g_alS2[grow * 2 + q] = s;
            else       g_alD2[grow * 2 + (q - 2)] = s;
        }
    }
}

// ---------------- layer2 gather: warp per node, fused alpha, plain loop ------
__global__ void __launch_bounds__(256) k_gath2() {
    if (blockIdx.x == 0) {   // self-clean for next replay
        if (threadIdx.x < 36) g_zmom[threadIdx.x] = 0.f;
        if (threadIdx.x >= 36 && threadIdx.x < 38) g_eamsum[threadIdx.x - 36] = 0.f;
    }
    int d = (blockIdx.x * 256 + threadIdx.x) >> 5;
    if (d >= NN) return;
    int lane = threadIdx.x & 31;
    int j = lane * 4;
    int h = lane >> 4;
    int p0 = d ? g_rowptr[d - 1] : 0;
    int p1 = g_rowptr[d];
    float v20 = g_v2[2 * h], v21 = g_v2[2 * h + 1];
    float aD = g_alD2[d * 2 + h];
    float4 acc = make_float4(0.f, 0.f, 0.f, 0.f);
    float ws = 0.f;
#pragma unroll 2
    for (int pos = p0; pos < p1; pos++) {
        int s = __ldg(&g_csr_src[pos]);
        float2 e2 = __ldg(&g_csr_ea[pos]);
        float a = __ldg(&g_alS2[s * 2 + h]) + aD + e2.x * v20 + e2.y * v21;
        a = a > 0.f ? a : 0.2f * a;
        float w = __expf(a);
        float4 v = *(const float4*)(g_A + (size_t)s * 128 + j);
        ws += w;
        acc.x += v.x * w; acc.y += v.y * w; acc.z += v.z * w; acc.w += v.w * w;
    }
    float r = 1.f / ws;
    acc.x *= r; acc.y *= r; acc.z *= r; acc.w *= r;
    *(float4*)(g_B + (size_t)d * 128 + j) = acc;
}

// ---------------- layer2 GraphNorm column stats ------------------------------
__global__ void k_colsum2(const float* __restrict__ X, int rpb) {
    int j = threadIdx.x;   // 128
    int r0 = blockIdx.x * rpb, r1 = min(r0 + rpb, NN);
    float s = 0.f, q = 0.f;
    for (int r = r0; r < r1; r++) {
        float v = X[(size_t)r * 128 + j];
        s += v;
        q += v * v;
    }
    atomicAdd(&g_colstats[j], s);
    atomicAdd(&g_colstats[256 + j], q);
}

// ---------------- classifier (inline layer2 norm + ELU) ----------------------
__global__ void k_cls(const float* __restrict__ Wc, const float* __restrict__ bc,
                      const float* __restrict__ b2, const float* __restrict__ ms2,
                      const float* __restrict__ gw2, const float* __restrict__ gb2,
                      float* __restrict__ out) {
    __shared__ float wc[128 * 13];
    __shared__ float sbc[13];
    __shared__ float cs[128], cf[128];
    for (int i = threadIdx.x; i < 128 * 13; i += 256) wc[i] = Wc[i];
    if (threadIdx.x < 13) sbc[threadIdx.x] = bc[threadIdx.x];
    if (threadIdx.x < 128) {
        int j = threadIdx.x;
        float invN = 1.0f / NN;
        float sum = g_colstats[j], sq = g_colstats[256 + j];
        float bj = b2[j];
        float m = sum * invN + bj;
        float cp = bj - m * ms2[j];
        float var = sq * invN + 2.f * cp * (sum * invN) + cp * cp;
        float rstd = rsqrtf(var + EPSN);
        cs[j] = gw2[j] * rstd;
        cf[j] = cp * gw2[j] * rstd + gb2[j];
    }
    __syncthreads();
    int warp = (blockIdx.x * 256 + threadIdx.x) >> 5;
    int lane = threadIdx.x & 31;
    int nw = (gridDim.x * 256) >> 5;
    for (int n = warp; n < NN; n += nw) {
        float4 hv = *(const float4*)(g_B + (size_t)n * 128 + lane * 4);
        int kb = lane * 4;
        float y0 = hv.x * cs[kb + 0] + cf[kb + 0]; y0 = y0 > 0.f ? y0 : expm1f(y0);
        float y1 = hv.y * cs[kb + 1] + cf[kb + 1]; y1 = y1 > 0.f ? y1 : expm1f(y1);
        float y2 = hv.z * cs[kb + 2] + cf[kb + 2]; y2 = y2 > 0.f ? y2 : expm1f(y2);
        float y3 = hv.w * cs[kb + 3] + cf[kb + 3]; y3 = y3 > 0.f ? y3 : expm1f(y3);
#pragma unroll
        for (int c = 0; c < 13; c++) {
            float p = y0 * wc[kb * 13 + c] + y1 * wc[(kb + 1) * 13 + c]
                    + y2 * wc[(kb + 2) * 13 + c] + y3 * wc[(kb + 3) * 13 + c];
            for (int o = 16; o; o >>= 1) p += __shfl_down_sync(0xFFFFFFFFu, p, o);
            if (lane == 0) out[n * 13 + c] = p + sbc[c];
        }
    }
}

// ---------------- launch ------------------------------------------------------
extern "C" void kernel_launch(void* const* d_in, const int* in_sizes, int n_in,
                              void* d_out, int out_size) {
    const float* x    = (const float*)d_in[0];
    const int*   ei   = (const int*)d_in[1];
    const float* ea   = (const float*)d_in[2];
    const float* W1   = (const float*)d_in[3];
    const float* We1  = (const float*)d_in[4];
    const float* as1  = (const float*)d_in[5];
    const float* ad1  = (const float*)d_in[6];
    const float* ae1  = (const float*)d_in[7];
    const float* b1   = (const float*)d_in[8];
    const float* gn1w = (const float*)d_in[9];
    const float* gn1b = (const float*)d_in[10];
    const float* gn1m = (const float*)d_in[11];
    const float* W2   = (const float*)d_in[12];
    const float* We2  = (const float*)d_in[13];
    const float* as2  = (const float*)d_in[14];
    const float* ad2  = (const float*)d_in[15];
    const float* ae2  = (const float*)d_in[16];
    const float* b2   = (const float*)d_in[17];
    const float* gn2w = (const float*)d_in[18];
    const float* gn2b = (const float*)d_in[19];
    const float* gn2m = (const float*)d_in[20];
    const float* Wc   = (const float*)d_in[21];
    const float* bc   = (const float*)d_in[22];
    float* out = (float*)d_out;

    float* pB;
    cudaGetSymbolAddress((void**)&pB, g_B);

    cudaFuncSetAttribute(k_gemm2f, cudaFuncAttributeMaxDynamicSharedMemorySize, 256 * XPAD * 4);

    int nb = (NN + 255) / 256;   // 196

    k_prepcm<<<516, 256>>>(ei, ea, We1, ae1, We2, ae2, W1, as1, ad1, W2, as2, ad2); // 0
    k_scan<<<nb, 256>>>(x);                                            // 1
    k_fill<<<(ET / 4 + 255) / 256, 256>>>(ei, ea);                     // 2
    k_gath1z<<<nb, 256>>>(x);                                          // 3  <- profiled
    k_gemm2f<<<(NN + 63) / 64, 256, 256 * XPAD * 4>>>(W1, W2, b1, gn1m, gn1w, gn1b); // 4
    k_gath2<<<(NN * 32 + 255) / 256, 256>>>();                         // 5
    k_colsum2<<<(NN + 127) / 128, 128>>>(pB, 128);                     // 6
    k_cls<<<512, 256>>>(Wc, bc, b2, gn2m, gn2w, gn2b, out);            // 7
}